// round 15
// baseline (speedup 1.0000x reference)
#include <cuda_runtime.h>
#include <cuda_bf16.h>
#include <stdint.h>

#define BB 4
#define CC 256
#define DKK 32
#define NN 4096

// ---------------- scratch (static device globals; no allocs) ----------------
__device__ __nv_bfloat16 g_X[BB * CC * NN];
__device__ __nv_bfloat16 g_W[384 * CC];
__device__ float         g_bias[384];
__device__ __nv_bfloat16 g_F[BB * DKK * NN];
__device__ __nv_bfloat16 g_G[BB * DKK * NN];
__device__ __nv_bfloat16 g_H[BB * CC * NN];
__device__ uint8_t       g_Hs[BB * CC * NN];                 // h*4096/Z in e4m3
__device__ uint16_t      g_E8[(size_t)BB * (NN / 2) * NN];   // e4m3 pairs [b][jp][i]
__device__ float         g_rZ[BB * NN];

// ---------------- helpers ----------------
__device__ __forceinline__ float fexp(float s) {
    float r;
    asm("ex2.approx.f32 %0, %1;" : "=f"(r) : "f"(s * 1.4426950408889634f));
    return r;
}
__device__ __forceinline__ uint32_t smem_u32(const void* p) {
    return (uint32_t)__cvta_generic_to_shared(p);
}
__device__ __forceinline__ void ldsm_x4(uint32_t* r, uint32_t addr) {
    asm volatile("ldmatrix.sync.aligned.m8n8.x4.shared.b16 {%0,%1,%2,%3}, [%4];\n"
                 : "=r"(r[0]), "=r"(r[1]), "=r"(r[2]), "=r"(r[3]) : "r"(addr));
}
__device__ __forceinline__ void ldsm_x4_t(uint32_t* r, uint32_t addr) {
    asm volatile("ldmatrix.sync.aligned.m8n8.x4.trans.shared.b16 {%0,%1,%2,%3}, [%4];\n"
                 : "=r"(r[0]), "=r"(r[1]), "=r"(r[2]), "=r"(r[3]) : "r"(addr));
}
__device__ __forceinline__ void mma_bf16(float* c, const uint32_t* a, uint32_t b0, uint32_t b1) {
    asm volatile("mma.sync.aligned.m16n8k16.row.col.f32.bf16.bf16.f32 "
                 "{%0,%1,%2,%3}, {%4,%5,%6,%7}, {%8,%9}, {%0,%1,%2,%3};\n"
                 : "+f"(c[0]), "+f"(c[1]), "+f"(c[2]), "+f"(c[3])
                 : "r"(a[0]), "r"(a[1]), "r"(a[2]), "r"(a[3]), "r"(b0), "r"(b1));
}
__device__ __forceinline__ void mma_fp8(float* c, const uint32_t* a, uint32_t b0, uint32_t b1) {
    asm volatile("mma.sync.aligned.m16n8k32.row.col.f32.e4m3.e4m3.f32 "
                 "{%0,%1,%2,%3}, {%4,%5,%6,%7}, {%8,%9}, {%0,%1,%2,%3};\n"
                 : "+f"(c[0]), "+f"(c[1]), "+f"(c[2]), "+f"(c[3])
                 : "r"(a[0]), "r"(a[1]), "r"(a[2]), "r"(a[3]), "r"(b0), "r"(b1));
}
__device__ __forceinline__ void cpasync16(uint32_t dst, const void* src) {
    asm volatile("cp.async.cg.shared.global [%0], [%1], 16;\n" :: "r"(dst), "l"(src));
}
__device__ __forceinline__ uint16_t pack_e4m3(float hi, float lo) {
    uint16_t r;
    asm("cvt.rn.satfinite.e4m3x2.f32 %0, %1, %2;" : "=h"(r) : "f"(hi), "f"(lo));
    return r;
}

// ============================================================================
// P0: x fp32 -> bf16
// ============================================================================
__global__ __launch_bounds__(256) void k_prep(const float* __restrict__ x)
{
    size_t idx = ((size_t)blockIdx.x * 256 + threadIdx.x) * 8;
    float4 a = *(const float4*)(x + idx);
    float4 b = *(const float4*)(x + idx + 4);
    uint4 o;
    __nv_bfloat162* op = (__nv_bfloat162*)&o;
    op[0] = __floats2bfloat162_rn(a.x, a.y);
    op[1] = __floats2bfloat162_rn(a.z, a.w);
    op[2] = __floats2bfloat162_rn(b.x, b.y);
    op[3] = __floats2bfloat162_rn(b.z, b.w);
    *(uint4*)&g_X[idx] = o;
}

// ============================================================================
// P1: pack W into g_W [384 x 256] bf16 (+ bias)
// ============================================================================
__global__ __launch_bounds__(64) void k_prepw(
    const float* __restrict__ Wf, const float* __restrict__ bf,
    const float* __restrict__ Wg, const float* __restrict__ bg,
    const float* __restrict__ Wh, const float* __restrict__ bh)
{
    int row = blockIdx.x;
    const float* src = nullptr; float bias = 0.f;
    if (row < 32)       { src = Wf + (size_t)row * CC;        bias = bf[row]; }
    else if (row < 64)  { src = Wg + (size_t)(row - 32) * CC; bias = bg[row - 32]; }
    else if (row < 320) { src = Wh + (size_t)(row - 64) * CC; bias = bh[row - 64]; }
    for (int c = threadIdx.x * 4; c < CC; c += 64 * 4) {
#pragma unroll
        for (int k = 0; k < 4; k++)
            g_W[(size_t)row * CC + c + k] = src ? __float2bfloat16(src[c + k]) : __float2bfloat16(0.f);
    }
    if (threadIdx.x == 0) g_bias[row] = bias;
}

// ============================================================================
// K1: projections via bf16 mma (measured, unchanged)
// ============================================================================
#define AST 40
#define EST 136

__global__ __launch_bounds__(256, 2) void k_proj_mma()
{
    __shared__ __nv_bfloat16 As[2][128 * AST];
    __shared__ __nv_bfloat16 Bs[2][32 * EST];

    const int it = blockIdx.x, ct = blockIdx.y, b = blockIdx.z;
    const int tid = threadIdx.x;
    const int lane = tid & 31, warp = tid >> 5;
    const int wm = warp >> 2, wn = warp & 3;

    const __nv_bfloat16* Ag = g_W + (size_t)(ct * 128) * CC;
    const __nv_bfloat16* Bg = g_X + (size_t)b * CC * NN + it * 128;

    auto loadA = [&](int st, int kb) {
        int k0 = kb * 32;
        int row = tid >> 2, cid = (tid & 3) * 8;
#pragma unroll
        for (int r = 0; r < 2; r++) {
            int rr = row + r * 64;
            cpasync16(smem_u32(&As[st][rr * AST + cid]), Ag + (size_t)rr * CC + k0 + cid);
        }
    };
    auto loadB = [&](int st, int kb) {
        int k0 = kb * 32;
        int row = tid >> 4, cid = (tid & 15) * 8;
#pragma unroll
        for (int r = 0; r < 2; r++) {
            int rr = row + r * 16;
            cpasync16(smem_u32(&Bs[st][rr * EST + cid]), Bg + (size_t)(k0 + rr) * NN + cid);
        }
    };

    float acc[4][4][4];
#pragma unroll
    for (int m = 0; m < 4; m++)
#pragma unroll
        for (int n = 0; n < 4; n++)
#pragma unroll
            for (int e = 0; e < 4; e++) acc[m][n][e] = 0.f;

    loadA(0, 0); loadB(0, 0);
    asm volatile("cp.async.commit_group;\n");
    loadA(1, 1); loadB(1, 1);
    asm volatile("cp.async.commit_group;\n");

    const int grp = lane >> 3, lr = lane & 7;
    const int KB = CC / 32;

    for (int kb = 0; kb < KB; kb++) {
        asm volatile("cp.async.wait_group 1;\n");
        __syncthreads();
        const int st = kb & 1;
        const uint32_t smA = smem_u32(&As[st][0]);
        const uint32_t smB = smem_u32(&Bs[st][0]);
#pragma unroll
        for (int ks = 0; ks < 32; ks += 16) {
            uint32_t a[4][4];
#pragma unroll
            for (int mt = 0; mt < 4; mt++) {
                int row = wm * 64 + mt * 16 + (grp & 1) * 8 + lr;
                int col = ks + (grp >> 1) * 8;
                ldsm_x4(a[mt], smA + (row * AST + col) * 2);
            }
            uint32_t bfr[2][4];
#pragma unroll
            for (int nt = 0; nt < 2; nt++) {
                int krow = ks + (grp & 1) * 8 + lr;
                int ncol = wn * 32 + nt * 16 + (grp >> 1) * 8;
                ldsm_x4_t(bfr[nt], smB + (krow * EST + ncol) * 2);
            }
#pragma unroll
            for (int mt = 0; mt < 4; mt++)
#pragma unroll
                for (int nf = 0; nf < 4; nf++)
                    mma_bf16(acc[mt][nf], a[mt], bfr[nf >> 1][(nf & 1) * 2], bfr[nf >> 1][(nf & 1) * 2 + 1]);
        }
        __syncthreads();
        if (kb + 2 < KB) { loadA(st, kb + 2); loadB(st, kb + 2); }
        asm volatile("cp.async.commit_group;\n");
    }

#pragma unroll
    for (int mt = 0; mt < 4; mt++) {
#pragma unroll
        for (int nf = 0; nf < 4; nf++) {
            int col = it * 128 + wn * 32 + nf * 8 + (lane & 3) * 2;
#pragma unroll
            for (int h = 0; h < 2; h++) {
                int row = ct * 128 + wm * 64 + mt * 16 + (lane >> 2) + h * 8;
                if (row >= 320) continue;
                float bias = g_bias[row];
                __nv_bfloat16* dst;
                if (row < 32)      dst = g_F + ((size_t)(b * DKK + row)) * NN;
                else if (row < 64) dst = g_G + ((size_t)(b * DKK + row - 32)) * NN;
                else               dst = g_H + ((size_t)(b * CC + row - 64)) * NN;
                float v0 = acc[mt][nf][2 * h]     + bias;
                float v1 = acc[mt][nf][2 * h + 1] + bias;
                *(__nv_bfloat162*)(dst + col) = __floats2bfloat162_rn(v0, v1);
            }
        }
    }
}

// ============================================================================
// K2: S^T layout (m=i, n=j); E stored as e4m3 j-pairs. (measured 58us; exp -> ex2.approx)
// ============================================================================
#define JST 72
#define FST 264

__global__ __launch_bounds__(256) void k_scores_mma()
{
    __shared__ __nv_bfloat16 gs[32 * JST];
    __shared__ __nv_bfloat16 fs[2][32 * FST];
    __shared__ float Zs[64];

    const int jt = blockIdx.x, b = blockIdx.y;
    const int tid = threadIdx.x;
    const int lane = tid & 31, warp = tid >> 5;
    const int wm = warp >> 1, wn = warp & 1;
    const int grp = lane >> 3, lr = lane & 7;
    const int j0 = jt * 64;

    {
        int row = tid >> 3, col = (tid & 7) * 8;
        uint4 v = *(const uint4*)(g_G + ((size_t)(b * DKK + row)) * NN + j0 + col);
        *(uint4*)&gs[row * JST + col] = v;
    }

    auto loadF = [&](int st, int ch) {
        const __nv_bfloat16* src = g_F + (size_t)b * DKK * NN + ch * 256;
#pragma unroll
        for (int r = 0; r < 4; r++) {
            int e = tid + r * 256;
            int row = e >> 5, col = (e & 31) * 8;
            cpasync16(smem_u32(&fs[st][row * FST + col]), src + (size_t)row * NN + col);
        }
    };

    loadF(0, 0);
    asm volatile("cp.async.commit_group;\n");
    loadF(1, 1);
    asm volatile("cp.async.commit_group;\n");
    __syncthreads();

    const uint32_t smG = smem_u32(gs);
    uint16_t* const E8b = g_E8 + (size_t)b * (NN / 2) * NN;

    float zacc[8];
#pragma unroll
    for (int r = 0; r < 8; r++) zacc[r] = 0.f;

    for (int ch = 0; ch < 16; ch++) {
        asm volatile("cp.async.wait_group 1;\n");
        __syncthreads();
        const int st = ch & 1;
        const uint32_t smF = smem_u32(&fs[st][0]);
        const int i0 = ch * 256;

        float acc[4][4][4];
#pragma unroll
        for (int m = 0; m < 4; m++)
#pragma unroll
            for (int n = 0; n < 4; n++)
#pragma unroll
                for (int e = 0; e < 4; e++) acc[m][n][e] = 0.f;

#pragma unroll
        for (int ks = 0; ks < 32; ks += 16) {
            uint32_t a[4][4];
#pragma unroll
            for (int mt = 0; mt < 4; mt++) {
                int row = ks + (grp >> 1) * 8 + lr;
                int col = wm * 64 + mt * 16 + (grp & 1) * 8;
                ldsm_x4_t(a[mt], smF + (row * FST + col) * 2);
            }
            uint32_t bfr[2][4];
#pragma unroll
            for (int nt = 0; nt < 2; nt++) {
                int krow = ks + (grp & 1) * 8 + lr;
                int ncol = wn * 32 + nt * 16 + (grp >> 1) * 8;
                ldsm_x4_t(bfr[nt], smG + (krow * JST + ncol) * 2);
            }
#pragma unroll
            for (int mt = 0; mt < 4; mt++)
#pragma unroll
                for (int nf = 0; nf < 4; nf++)
                    mma_bf16(acc[mt][nf], a[mt], bfr[nf >> 1][(nf & 1) * 2], bfr[nf >> 1][(nf & 1) * 2 + 1]);
        }

#pragma unroll
        for (int mt = 0; mt < 4; mt++) {
#pragma unroll
            for (int nf = 0; nf < 4; nf++) {
                int j = j0 + wn * 32 + nf * 8 + (lane & 3) * 2;
#pragma unroll
                for (int h = 0; h < 2; h++) {
                    int i = i0 + wm * 64 + mt * 16 + (lane >> 2) + h * 8;
                    float e0 = fexp(acc[mt][nf][2 * h]);
                    float e1 = fexp(acc[mt][nf][2 * h + 1]);
                    zacc[nf * 2 + 0] += e0;
                    zacc[nf * 2 + 1] += e1;
                    E8b[((size_t)(j >> 1) << 12) + i] = pack_e4m3(e1, e0);
                }
            }
        }
        __syncthreads();
        if (ch + 2 < 16) loadF(st, ch + 2);
        asm volatile("cp.async.commit_group;\n");
    }

    if (tid < 64) Zs[tid] = 0.f;
    __syncthreads();
#pragma unroll
    for (int r = 0; r < 8; r++) {
        zacc[r] += __shfl_xor_sync(0xffffffffu, zacc[r], 4);
        zacc[r] += __shfl_xor_sync(0xffffffffu, zacc[r], 8);
        zacc[r] += __shfl_xor_sync(0xffffffffu, zacc[r], 16);
    }
    if (lane < 4) {
#pragma unroll
        for (int nf = 0; nf < 4; nf++) {
#pragma unroll
            for (int p = 0; p < 2; p++)
                atomicAdd(&Zs[wn * 32 + nf * 8 + lane * 2 + p], zacc[nf * 2 + p]);
        }
    }
    __syncthreads();
    if (tid < 64) g_rZ[b * NN + j0 + tid] = 1.0f / Zs[tid];
}

// ============================================================================
// K2c: g_Hs[c][j] = e4m3( h[c][j] * 4096/Z[j] )
// ============================================================================
__global__ __launch_bounds__(256) void k_scaleh()
{
    size_t idx = ((size_t)blockIdx.x * 256 + threadIdx.x) * 8;
    int b = (int)(idx >> 20);
    int n = (int)(idx & (NN - 1));
    uint4 raw = *(uint4*)&g_H[idx];
    __nv_bfloat162* hp = (__nv_bfloat162*)&raw;
    const float* rz = g_rZ + b * NN + n;
    uint16_t h4[4];
#pragma unroll
    for (int p = 0; p < 4; p++) {
        float s0 = 4096.0f * rz[2 * p];
        float s1 = 4096.0f * rz[2 * p + 1];
        float v0 = __bfloat162float(__low2bfloat16(hp[p]))  * s0;
        float v1 = __bfloat162float(__high2bfloat16(hp[p])) * s1;
        h4[p] = pack_e4m3(v1, v0);
    }
    uint2 o;
    o.x = (uint32_t)h4[0] | ((uint32_t)h4[1] << 16);
    o.y = (uint32_t)h4[2] | ((uint32_t)h4[3] << 16);
    *(uint2*)&g_Hs[idx] = o;
}

// ============================================================================
// K3: out = (Hs @ E)/4096 + x via FP8 mma. CTA 128x128, k-chunk 32, 3-stage,
// CROSS-ITERATION FRAGMENT DOUBLE-BUFFER: ldsm frags(kb+1) before mma(kb).
// 8 warps 2x4, warp 64x32, occ 2.
// ============================================================================
#define K3A 24
#define K3E 136

__global__ __launch_bounds__(256, 2) void k_attn_out(
    const float* __restrict__ x, float* __restrict__ out)
{
    __shared__ uint16_t As[3][128 * K3A];
    __shared__ uint16_t Es[3][16 * K3E];

    const int it = blockIdx.x, ct = blockIdx.y, b = blockIdx.z;
    const int tid = threadIdx.x;
    const int lane = tid & 31, warp = tid >> 5;
    const int wm = warp >> 2, wn = warp & 3;

    const uint8_t*  Ag = g_Hs + (size_t)(b * CC + ct * 128) * NN;
    const uint16_t* Eg = g_E8 + (size_t)b * (NN / 2) * NN + it * 128;

    auto loadTile = [&](int kb) {
        const int st = kb % 3;
        int k0 = kb * 32;
        {   // A: 128 rows x 32B
            int row = tid >> 1, seg = (tid & 1) * 16;
            cpasync16(smem_u32(&As[st][row * K3A + (tid & 1) * 8]), Ag + (size_t)row * NN + k0 + seg);
        }
        {   // E: 16 jp-rows x 256B
            int kp0 = kb * 16;
            int row = tid >> 4, col = (tid & 15) * 8;
            cpasync16(smem_u32(&Es[st][row * K3E + col]), Eg + (size_t)(kp0 + row) * NN + col);
        }
    };

    const int grp = lane >> 3, lr = lane & 7;

    auto ldFrags = [&](int st, uint32_t a[4][4], uint32_t bfr[2][4]) {
        const uint32_t smA = smem_u32(&As[st][0]);
        const uint32_t smE = smem_u32(&Es[st][0]);
#pragma unroll
        for (int mt = 0; mt < 4; mt++) {
            int row = wm * 64 + mt * 16 + (grp & 1) * 8 + lr;
            int col = (grp >> 1) * 8;
            ldsm_x4(a[mt], smA + (row * K3A + col) * 2);
        }
#pragma unroll
        for (int nt = 0; nt < 2; nt++) {
            int krow = (grp & 1) * 8 + lr;
            int ncol = wn * 32 + nt * 16 + (grp >> 1) * 8;
            ldsm_x4_t(bfr[nt], smE + (krow * K3E + ncol) * 2);
        }
    };

    float acc[4][4][4];
#pragma unroll
    for (int m = 0; m < 4; m++)
#pragma unroll
        for (int n = 0; n < 4; n++)
#pragma unroll
            for (int e = 0; e < 4; e++) acc[m][n][e] = 0.f;

    // prologue: stages 0,1 in flight; stage0 frags in regs; stage2 loading
    loadTile(0);
    asm volatile("cp.async.commit_group;\n");
    loadTile(1);
    asm volatile("cp.async.commit_group;\n");
    asm volatile("cp.async.wait_group 1;\n");   // stage 0 ready
    __syncthreads();
    loadTile(2);
    asm volatile("cp.async.commit_group;\n");   // pending {1,2}

    uint32_t aF[2][4][4], bF[2][2][4];
    ldFrags(0, aF[0], bF[0]);

    const int KB = NN / 32;   // 128
    for (int kb = 0; kb < KB; kb++) {
        const int cur = kb & 1, nxt = cur ^ 1;

        asm volatile("cp.async.wait_group 1;\n");   // stage kb+1 ready (pending {kb+2})
        __syncthreads();   // all warps did iter kb-1 ldsm (stage kb%3 free for write)

        if (kb + 3 < KB) loadTile(kb + 3);          // into stage kb%3
        asm volatile("cp.async.commit_group;\n");   // pending {kb+2, kb+3}

        if (kb + 1 < KB) ldFrags((kb + 1) % 3, aF[nxt], bF[nxt]);

#pragma unroll
        for (int mt = 0; mt < 4; mt++)
#pragma unroll
            for (int nf = 0; nf < 4; nf++)
                mma_fp8(acc[mt][nf], aF[cur][mt],
                        bF[cur][nf >> 1][(nf & 1) * 2], bF[cur][nf >> 1][(nf & 1) * 2 + 1]);
    }

    // epilogue: out = acc/4096 + x
    const float INVN = 1.0f / 4096.0f;
#pragma unroll
    for (int mt = 0; mt < 4; mt++) {
#pragma unroll
        for (int nf = 0; nf < 4; nf++) {
            int row = ct * 128 + wm * 64 + mt * 16 + (lane >> 2);
            int col = it * 128 + wn * 32 + nf * 8 + (lane & 3) * 2;
            size_t base = ((size_t)(b * CC + row)) * NN + col;
            float2 xv = *(const float2*)(x + base);
            float2 o0;
            o0.x = fmaf(acc[mt][nf][0], INVN, xv.x);
            o0.y = fmaf(acc[mt][nf][1], INVN, xv.y);
            *(float2*)(out + base) = o0;
            size_t base2 = base + (size_t)8 * NN;
            float2 xv2 = *(const float2*)(x + base2);
            float2 o1;
            o1.x = fmaf(acc[mt][nf][2], INVN, xv2.x);
            o1.y = fmaf(acc[mt][nf][3], INVN, xv2.y);
            *(float2*)(out + base2) = o1;
        }
    }
}

// ============================================================================
extern "C" void kernel_launch(void* const* d_in, const int* in_sizes, int n_in,
                              void* d_out, int out_size)
{
    const float* x  = (const float*)d_in[0];
    const float* Wf = (const float*)d_in[1];
    const float* bf = (const float*)d_in[2];
    const float* Wg = (const float*)d_in[3];
    const float* bg = (const float*)d_in[4];
    const float* Wh = (const float*)d_in[5];
    const float* bh = (const float*)d_in[6];
    float* out = (float*)d_out;

    k_prep      <<<2048, 256>>>(x);
    k_prepw     <<<384, 64>>>(Wf, bf, Wg, bg, Wh, bh);
    k_proj_mma  <<<dim3(32, 3, 4), 256>>>();
    k_scores_mma<<<dim3(64, 4),    256>>>();
    k_scaleh    <<<2048,           256>>>();
    k_attn_out  <<<dim3(32, 2, 4), 256>>>(x, out);
}

// round 16
// speedup vs baseline: 1.0473x; 1.0473x over previous
#include <cuda_runtime.h>
#include <cuda_bf16.h>
#include <stdint.h>

#define BB 4
#define CC 256
#define DKK 32
#define NN 4096

// ---------------- scratch (static device globals; no allocs) ----------------
__device__ __nv_bfloat16 g_X[BB * CC * NN];
__device__ __nv_bfloat16 g_W[384 * CC];
__device__ float         g_bias[384];
__device__ __nv_bfloat16 g_F[BB * DKK * NN];
__device__ __nv_bfloat16 g_G[BB * DKK * NN];
__device__ __nv_bfloat16 g_H[BB * CC * NN];
__device__ uint8_t       g_Hs[BB * CC * NN];                 // h*4096/Z in e4m3
__device__ uint16_t      g_E8[(size_t)BB * (NN / 2) * NN];   // e4m3 pairs [b][jp][i]
__device__ float         g_rZ[BB * NN];

// ---------------- helpers ----------------
__device__ __forceinline__ float fexp(float s) {
    float r;
    asm("ex2.approx.f32 %0, %1;" : "=f"(r) : "f"(s * 1.4426950408889634f));
    return r;
}
__device__ __forceinline__ uint32_t smem_u32(const void* p) {
    return (uint32_t)__cvta_generic_to_shared(p);
}
__device__ __forceinline__ void ldsm_x4(uint32_t* r, uint32_t addr) {
    asm volatile("ldmatrix.sync.aligned.m8n8.x4.shared.b16 {%0,%1,%2,%3}, [%4];\n"
                 : "=r"(r[0]), "=r"(r[1]), "=r"(r[2]), "=r"(r[3]) : "r"(addr));
}
__device__ __forceinline__ void ldsm_x4_t(uint32_t* r, uint32_t addr) {
    asm volatile("ldmatrix.sync.aligned.m8n8.x4.trans.shared.b16 {%0,%1,%2,%3}, [%4];\n"
                 : "=r"(r[0]), "=r"(r[1]), "=r"(r[2]), "=r"(r[3]) : "r"(addr));
}
__device__ __forceinline__ void mma_bf16(float* c, const uint32_t* a, uint32_t b0, uint32_t b1) {
    asm volatile("mma.sync.aligned.m16n8k16.row.col.f32.bf16.bf16.f32 "
                 "{%0,%1,%2,%3}, {%4,%5,%6,%7}, {%8,%9}, {%0,%1,%2,%3};\n"
                 : "+f"(c[0]), "+f"(c[1]), "+f"(c[2]), "+f"(c[3])
                 : "r"(a[0]), "r"(a[1]), "r"(a[2]), "r"(a[3]), "r"(b0), "r"(b1));
}
__device__ __forceinline__ void mma_fp8(float* c, const uint32_t* a, uint32_t b0, uint32_t b1) {
    asm volatile("mma.sync.aligned.m16n8k32.row.col.f32.e4m3.e4m3.f32 "
                 "{%0,%1,%2,%3}, {%4,%5,%6,%7}, {%8,%9}, {%0,%1,%2,%3};\n"
                 : "+f"(c[0]), "+f"(c[1]), "+f"(c[2]), "+f"(c[3])
                 : "r"(a[0]), "r"(a[1]), "r"(a[2]), "r"(a[3]), "r"(b0), "r"(b1));
}
__device__ __forceinline__ void cpasync16(uint32_t dst, const void* src) {
    asm volatile("cp.async.cg.shared.global [%0], [%1], 16;\n" :: "r"(dst), "l"(src));
}
__device__ __forceinline__ uint16_t pack_e4m3(float hi, float lo) {
    uint16_t r;
    asm("cvt.rn.satfinite.e4m3x2.f32 %0, %1, %2;" : "=h"(r) : "f"(hi), "f"(lo));
    return r;
}

// ============================================================================
// P0: x fp32 -> bf16
// ============================================================================
__global__ __launch_bounds__(256) void k_prep(const float* __restrict__ x)
{
    size_t idx = ((size_t)blockIdx.x * 256 + threadIdx.x) * 8;
    float4 a = *(const float4*)(x + idx);
    float4 b = *(const float4*)(x + idx + 4);
    uint4 o;
    __nv_bfloat162* op = (__nv_bfloat162*)&o;
    op[0] = __floats2bfloat162_rn(a.x, a.y);
    op[1] = __floats2bfloat162_rn(a.z, a.w);
    op[2] = __floats2bfloat162_rn(b.x, b.y);
    op[3] = __floats2bfloat162_rn(b.z, b.w);
    *(uint4*)&g_X[idx] = o;
}

// ============================================================================
// P1: pack W into g_W [384 x 256] bf16 (+ bias)
// ============================================================================
__global__ __launch_bounds__(64) void k_prepw(
    const float* __restrict__ Wf, const float* __restrict__ bf,
    const float* __restrict__ Wg, const float* __restrict__ bg,
    const float* __restrict__ Wh, const float* __restrict__ bh)
{
    int row = blockIdx.x;
    const float* src = nullptr; float bias = 0.f;
    if (row < 32)       { src = Wf + (size_t)row * CC;        bias = bf[row]; }
    else if (row < 64)  { src = Wg + (size_t)(row - 32) * CC; bias = bg[row - 32]; }
    else if (row < 320) { src = Wh + (size_t)(row - 64) * CC; bias = bh[row - 64]; }
    for (int c = threadIdx.x * 4; c < CC; c += 64 * 4) {
#pragma unroll
        for (int k = 0; k < 4; k++)
            g_W[(size_t)row * CC + c + k] = src ? __float2bfloat16(src[c + k]) : __float2bfloat16(0.f);
    }
    if (threadIdx.x == 0) g_bias[row] = bias;
}

// ============================================================================
// K1: projections via bf16 mma (measured, unchanged)
// ============================================================================
#define AST 40
#define EST 136

__global__ __launch_bounds__(256, 2) void k_proj_mma()
{
    __shared__ __nv_bfloat16 As[2][128 * AST];
    __shared__ __nv_bfloat16 Bs[2][32 * EST];

    const int it = blockIdx.x, ct = blockIdx.y, b = blockIdx.z;
    const int tid = threadIdx.x;
    const int lane = tid & 31, warp = tid >> 5;
    const int wm = warp >> 2, wn = warp & 3;

    const __nv_bfloat16* Ag = g_W + (size_t)(ct * 128) * CC;
    const __nv_bfloat16* Bg = g_X + (size_t)b * CC * NN + it * 128;

    auto loadA = [&](int st, int kb) {
        int k0 = kb * 32;
        int row = tid >> 2, cid = (tid & 3) * 8;
#pragma unroll
        for (int r = 0; r < 2; r++) {
            int rr = row + r * 64;
            cpasync16(smem_u32(&As[st][rr * AST + cid]), Ag + (size_t)rr * CC + k0 + cid);
        }
    };
    auto loadB = [&](int st, int kb) {
        int k0 = kb * 32;
        int row = tid >> 4, cid = (tid & 15) * 8;
#pragma unroll
        for (int r = 0; r < 2; r++) {
            int rr = row + r * 16;
            cpasync16(smem_u32(&Bs[st][rr * EST + cid]), Bg + (size_t)(k0 + rr) * NN + cid);
        }
    };

    float acc[4][4][4];
#pragma unroll
    for (int m = 0; m < 4; m++)
#pragma unroll
        for (int n = 0; n < 4; n++)
#pragma unroll
            for (int e = 0; e < 4; e++) acc[m][n][e] = 0.f;

    loadA(0, 0); loadB(0, 0);
    asm volatile("cp.async.commit_group;\n");
    loadA(1, 1); loadB(1, 1);
    asm volatile("cp.async.commit_group;\n");

    const int grp = lane >> 3, lr = lane & 7;
    const int KB = CC / 32;

    for (int kb = 0; kb < KB; kb++) {
        asm volatile("cp.async.wait_group 1;\n");
        __syncthreads();
        const int st = kb & 1;
        const uint32_t smA = smem_u32(&As[st][0]);
        const uint32_t smB = smem_u32(&Bs[st][0]);
#pragma unroll
        for (int ks = 0; ks < 32; ks += 16) {
            uint32_t a[4][4];
#pragma unroll
            for (int mt = 0; mt < 4; mt++) {
                int row = wm * 64 + mt * 16 + (grp & 1) * 8 + lr;
                int col = ks + (grp >> 1) * 8;
                ldsm_x4(a[mt], smA + (row * AST + col) * 2);
            }
            uint32_t bfr[2][4];
#pragma unroll
            for (int nt = 0; nt < 2; nt++) {
                int krow = ks + (grp & 1) * 8 + lr;
                int ncol = wn * 32 + nt * 16 + (grp >> 1) * 8;
                ldsm_x4_t(bfr[nt], smB + (krow * EST + ncol) * 2);
            }
#pragma unroll
            for (int mt = 0; mt < 4; mt++)
#pragma unroll
                for (int nf = 0; nf < 4; nf++)
                    mma_bf16(acc[mt][nf], a[mt], bfr[nf >> 1][(nf & 1) * 2], bfr[nf >> 1][(nf & 1) * 2 + 1]);
        }
        __syncthreads();
        if (kb + 2 < KB) { loadA(st, kb + 2); loadB(st, kb + 2); }
        asm volatile("cp.async.commit_group;\n");
    }

#pragma unroll
    for (int mt = 0; mt < 4; mt++) {
#pragma unroll
        for (int nf = 0; nf < 4; nf++) {
            int col = it * 128 + wn * 32 + nf * 8 + (lane & 3) * 2;
#pragma unroll
            for (int h = 0; h < 2; h++) {
                int row = ct * 128 + wm * 64 + mt * 16 + (lane >> 2) + h * 8;
                if (row >= 320) continue;
                float bias = g_bias[row];
                __nv_bfloat16* dst;
                if (row < 32)      dst = g_F + ((size_t)(b * DKK + row)) * NN;
                else if (row < 64) dst = g_G + ((size_t)(b * DKK + row - 32)) * NN;
                else               dst = g_H + ((size_t)(b * CC + row - 64)) * NN;
                float v0 = acc[mt][nf][2 * h]     + bias;
                float v1 = acc[mt][nf][2 * h + 1] + bias;
                *(__nv_bfloat162*)(dst + col) = __floats2bfloat162_rn(v0, v1);
            }
        }
    }
}

// ============================================================================
// K2: S^T layout (m=i, n=j); E stored as e4m3 j-pairs; ex2.approx exp.
// (measured 49.4us, unchanged)
// ============================================================================
#define JST 72
#define FST 264

__global__ __launch_bounds__(256) void k_scores_mma()
{
    __shared__ __nv_bfloat16 gs[32 * JST];
    __shared__ __nv_bfloat16 fs[2][32 * FST];
    __shared__ float Zs[64];

    const int jt = blockIdx.x, b = blockIdx.y;
    const int tid = threadIdx.x;
    const int lane = tid & 31, warp = tid >> 5;
    const int wm = warp >> 1, wn = warp & 1;
    const int grp = lane >> 3, lr = lane & 7;
    const int j0 = jt * 64;

    {
        int row = tid >> 3, col = (tid & 7) * 8;
        uint4 v = *(const uint4*)(g_G + ((size_t)(b * DKK + row)) * NN + j0 + col);
        *(uint4*)&gs[row * JST + col] = v;
    }

    auto loadF = [&](int st, int ch) {
        const __nv_bfloat16* src = g_F + (size_t)b * DKK * NN + ch * 256;
#pragma unroll
        for (int r = 0; r < 4; r++) {
            int e = tid + r * 256;
            int row = e >> 5, col = (e & 31) * 8;
            cpasync16(smem_u32(&fs[st][row * FST + col]), src + (size_t)row * NN + col);
        }
    };

    loadF(0, 0);
    asm volatile("cp.async.commit_group;\n");
    loadF(1, 1);
    asm volatile("cp.async.commit_group;\n");
    __syncthreads();

    const uint32_t smG = smem_u32(gs);
    uint16_t* const E8b = g_E8 + (size_t)b * (NN / 2) * NN;

    float zacc[8];
#pragma unroll
    for (int r = 0; r < 8; r++) zacc[r] = 0.f;

    for (int ch = 0; ch < 16; ch++) {
        asm volatile("cp.async.wait_group 1;\n");
        __syncthreads();
        const int st = ch & 1;
        const uint32_t smF = smem_u32(&fs[st][0]);
        const int i0 = ch * 256;

        float acc[4][4][4];
#pragma unroll
        for (int m = 0; m < 4; m++)
#pragma unroll
            for (int n = 0; n < 4; n++)
#pragma unroll
                for (int e = 0; e < 4; e++) acc[m][n][e] = 0.f;

#pragma unroll
        for (int ks = 0; ks < 32; ks += 16) {
            uint32_t a[4][4];
#pragma unroll
            for (int mt = 0; mt < 4; mt++) {
                int row = ks + (grp >> 1) * 8 + lr;
                int col = wm * 64 + mt * 16 + (grp & 1) * 8;
                ldsm_x4_t(a[mt], smF + (row * FST + col) * 2);
            }
            uint32_t bfr[2][4];
#pragma unroll
            for (int nt = 0; nt < 2; nt++) {
                int krow = ks + (grp & 1) * 8 + lr;
                int ncol = wn * 32 + nt * 16 + (grp >> 1) * 8;
                ldsm_x4_t(bfr[nt], smG + (krow * JST + ncol) * 2);
            }
#pragma unroll
            for (int mt = 0; mt < 4; mt++)
#pragma unroll
                for (int nf = 0; nf < 4; nf++)
                    mma_bf16(acc[mt][nf], a[mt], bfr[nf >> 1][(nf & 1) * 2], bfr[nf >> 1][(nf & 1) * 2 + 1]);
        }

#pragma unroll
        for (int mt = 0; mt < 4; mt++) {
#pragma unroll
            for (int nf = 0; nf < 4; nf++) {
                int j = j0 + wn * 32 + nf * 8 + (lane & 3) * 2;
#pragma unroll
                for (int h = 0; h < 2; h++) {
                    int i = i0 + wm * 64 + mt * 16 + (lane >> 2) + h * 8;
                    float e0 = fexp(acc[mt][nf][2 * h]);
                    float e1 = fexp(acc[mt][nf][2 * h + 1]);
                    zacc[nf * 2 + 0] += e0;
                    zacc[nf * 2 + 1] += e1;
                    E8b[((size_t)(j >> 1) << 12) + i] = pack_e4m3(e1, e0);
                }
            }
        }
        __syncthreads();
        if (ch + 2 < 16) loadF(st, ch + 2);
        asm volatile("cp.async.commit_group;\n");
    }

    if (tid < 64) Zs[tid] = 0.f;
    __syncthreads();
#pragma unroll
    for (int r = 0; r < 8; r++) {
        zacc[r] += __shfl_xor_sync(0xffffffffu, zacc[r], 4);
        zacc[r] += __shfl_xor_sync(0xffffffffu, zacc[r], 8);
        zacc[r] += __shfl_xor_sync(0xffffffffu, zacc[r], 16);
    }
    if (lane < 4) {
#pragma unroll
        for (int nf = 0; nf < 4; nf++) {
#pragma unroll
            for (int p = 0; p < 2; p++)
                atomicAdd(&Zs[wn * 32 + nf * 8 + lane * 2 + p], zacc[nf * 2 + p]);
        }
    }
    __syncthreads();
    if (tid < 64) g_rZ[b * NN + j0 + tid] = 1.0f / Zs[tid];
}

// ============================================================================
// K2c: g_Hs[c][j] = e4m3( h[c][j] * 4096/Z[j] )
// ============================================================================
__global__ __launch_bounds__(256) void k_scaleh()
{
    size_t idx = ((size_t)blockIdx.x * 256 + threadIdx.x) * 8;
    int b = (int)(idx >> 20);
    int n = (int)(idx & (NN - 1));
    uint4 raw = *(uint4*)&g_H[idx];
    __nv_bfloat162* hp = (__nv_bfloat162*)&raw;
    const float* rz = g_rZ + b * NN + n;
    uint16_t h4[4];
#pragma unroll
    for (int p = 0; p < 4; p++) {
        float s0 = 4096.0f * rz[2 * p];
        float s1 = 4096.0f * rz[2 * p + 1];
        float v0 = __bfloat162float(__low2bfloat16(hp[p]))  * s0;
        float v1 = __bfloat162float(__high2bfloat16(hp[p])) * s1;
        h4[p] = pack_e4m3(v1, v0);
    }
    uint2 o;
    o.x = (uint32_t)h4[0] | ((uint32_t)h4[1] << 16);
    o.y = (uint32_t)h4[2] | ((uint32_t)h4[3] << 16);
    *(uint2*)&g_Hs[idx] = o;
}

// ============================================================================
// K3: out = (Hs @ E)/4096 + x via FP8 mma. EXACT R14-measured version:
// CTA 128x128, k-chunk 32, 3-stage single-sync, in-loop ldsm. occ 2.
// ============================================================================
#define K3A 24
#define K3E 136

__global__ __launch_bounds__(256, 2) void k_attn_out(
    const float* __restrict__ x, float* __restrict__ out)
{
    __shared__ uint16_t As[3][128 * K3A];
    __shared__ uint16_t Es[3][16 * K3E];

    const int it = blockIdx.x, ct = blockIdx.y, b = blockIdx.z;
    const int tid = threadIdx.x;
    const int lane = tid & 31, warp = tid >> 5;
    const int wm = warp >> 2, wn = warp & 3;

    const uint8_t*  Ag = g_Hs + (size_t)(b * CC + ct * 128) * NN;
    const uint16_t* Eg = g_E8 + (size_t)b * (NN / 2) * NN + it * 128;

    auto loadA = [&](int st, int kb) {
        int k0 = kb * 32;
        int row = tid >> 1, seg = (tid & 1) * 16;
        cpasync16(smem_u32(&As[st][row * K3A + (tid & 1) * 8]), Ag + (size_t)row * NN + k0 + seg);
    };
    auto loadE = [&](int st, int kb) {
        int kp0 = kb * 16;
        int row = tid >> 4, col = (tid & 15) * 8;
        cpasync16(smem_u32(&Es[st][row * K3E + col]), Eg + (size_t)(kp0 + row) * NN + col);
    };

    float acc[4][4][4];
#pragma unroll
    for (int m = 0; m < 4; m++)
#pragma unroll
        for (int n = 0; n < 4; n++)
#pragma unroll
            for (int e = 0; e < 4; e++) acc[m][n][e] = 0.f;

    loadA(0, 0); loadE(0, 0);
    asm volatile("cp.async.commit_group;\n");
    loadA(1, 1); loadE(1, 1);
    asm volatile("cp.async.commit_group;\n");

    const int grp = lane >> 3, lr = lane & 7;
    const int KB = NN / 32;   // 128

    for (int kb = 0; kb < KB; kb++) {
        asm volatile("cp.async.wait_group 1;\n");
        __syncthreads();

        if (kb + 2 < KB) {
            int st2 = (kb + 2) % 3;
            loadA(st2, kb + 2); loadE(st2, kb + 2);
        }
        asm volatile("cp.async.commit_group;\n");

        const int st = kb % 3;
        const uint32_t smA = smem_u32(&As[st][0]);
        const uint32_t smE = smem_u32(&Es[st][0]);

        uint32_t a[4][4];
#pragma unroll
        for (int mt = 0; mt < 4; mt++) {
            int row = wm * 64 + mt * 16 + (grp & 1) * 8 + lr;
            int col = (grp >> 1) * 8;
            ldsm_x4(a[mt], smA + (row * K3A + col) * 2);
        }
        uint32_t bfr[2][4];
#pragma unroll
        for (int nt = 0; nt < 2; nt++) {
            int krow = (grp & 1) * 8 + lr;
            int ncol = wn * 32 + nt * 16 + (grp >> 1) * 8;
            ldsm_x4_t(bfr[nt], smE + (krow * K3E + ncol) * 2);
        }
#pragma unroll
        for (int mt = 0; mt < 4; mt++)
#pragma unroll
            for (int nf = 0; nf < 4; nf++)
                mma_fp8(acc[mt][nf], a[mt], bfr[nf >> 1][(nf & 1) * 2], bfr[nf >> 1][(nf & 1) * 2 + 1]);
    }

    // epilogue: out = acc/4096 + x
    const float INVN = 1.0f / 4096.0f;
#pragma unroll
    for (int mt = 0; mt < 4; mt++) {
#pragma unroll
        for (int nf = 0; nf < 4; nf++) {
            int row = ct * 128 + wm * 64 + mt * 16 + (lane >> 2);
            int col = it * 128 + wn * 32 + nf * 8 + (lane & 3) * 2;
            size_t base = ((size_t)(b * CC + row)) * NN + col;
            float2 xv = *(const float2*)(x + base);
            float2 o0;
            o0.x = fmaf(acc[mt][nf][0], INVN, xv.x);
            o0.y = fmaf(acc[mt][nf][1], INVN, xv.y);
            *(float2*)(out + base) = o0;
            size_t base2 = base + (size_t)8 * NN;
            float2 xv2 = *(const float2*)(x + base2);
            float2 o1;
            o1.x = fmaf(acc[mt][nf][2], INVN, xv2.x);
            o1.y = fmaf(acc[mt][nf][3], INVN, xv2.y);
            *(float2*)(out + base2) = o1;
        }
    }
}

// ============================================================================
extern "C" void kernel_launch(void* const* d_in, const int* in_sizes, int n_in,
                              void* d_out, int out_size)
{
    const float* x  = (const float*)d_in[0];
    const float* Wf = (const float*)d_in[1];
    const float* bf = (const float*)d_in[2];
    const float* Wg = (const float*)d_in[3];
    const float* bg = (const float*)d_in[4];
    const float* Wh = (const float*)d_in[5];
    const float* bh = (const float*)d_in[6];
    float* out = (float*)d_out;

    k_prep      <<<2048, 256>>>(x);
    k_prepw     <<<384, 64>>>(Wf, bf, Wg, bg, Wh, bh);
    k_proj_mma  <<<dim3(32, 3, 4), 256>>>();
    k_scores_mma<<<dim3(64, 4),    256>>>();
    k_scaleh    <<<2048,           256>>>();
    k_attn_out  <<<dim3(32, 2, 4), 256>>>(x, out);
}

// round 17
// speedup vs baseline: 1.1235x; 1.0728x over previous
#include <cuda_runtime.h>
#include <cuda_bf16.h>
#include <stdint.h>

#define BB 4
#define CC 256
#define DKK 32
#define NN 4096

// ---------------- scratch (static device globals; no allocs) ----------------
__device__ __nv_bfloat16 g_X[BB * CC * NN];
__device__ __nv_bfloat16 g_W[384 * CC];
__device__ float         g_bias[384];
__device__ __nv_bfloat16 g_F[BB * DKK * NN];
__device__ __nv_bfloat16 g_G[BB * DKK * NN];
__device__ __nv_bfloat16 g_H[BB * CC * NN];
__device__ uint8_t       g_Hs[BB * CC * NN];                 // h*4096/Z in e4m3
__device__ uint16_t      g_E8[(size_t)BB * (NN / 2) * NN];   // e4m3 pairs [b][jp][i]
__device__ float         g_rZ[BB * NN];

// ---------------- helpers ----------------
__device__ __forceinline__ float fexp(float s) {
    float r;
    asm("ex2.approx.f32 %0, %1;" : "=f"(r) : "f"(s * 1.4426950408889634f));
    return r;
}
__device__ __forceinline__ uint32_t smem_u32(const void* p) {
    return (uint32_t)__cvta_generic_to_shared(p);
}
__device__ __forceinline__ void ldsm_x4(uint32_t* r, uint32_t addr) {
    asm volatile("ldmatrix.sync.aligned.m8n8.x4.shared.b16 {%0,%1,%2,%3}, [%4];\n"
                 : "=r"(r[0]), "=r"(r[1]), "=r"(r[2]), "=r"(r[3]) : "r"(addr));
}
__device__ __forceinline__ void ldsm_x4_t(uint32_t* r, uint32_t addr) {
    asm volatile("ldmatrix.sync.aligned.m8n8.x4.trans.shared.b16 {%0,%1,%2,%3}, [%4];\n"
                 : "=r"(r[0]), "=r"(r[1]), "=r"(r[2]), "=r"(r[3]) : "r"(addr));
}
__device__ __forceinline__ void mma_bf16(float* c, const uint32_t* a, uint32_t b0, uint32_t b1) {
    asm volatile("mma.sync.aligned.m16n8k16.row.col.f32.bf16.bf16.f32 "
                 "{%0,%1,%2,%3}, {%4,%5,%6,%7}, {%8,%9}, {%0,%1,%2,%3};\n"
                 : "+f"(c[0]), "+f"(c[1]), "+f"(c[2]), "+f"(c[3])
                 : "r"(a[0]), "r"(a[1]), "r"(a[2]), "r"(a[3]), "r"(b0), "r"(b1));
}
__device__ __forceinline__ void mma_fp8(float* c, const uint32_t* a, uint32_t b0, uint32_t b1) {
    asm volatile("mma.sync.aligned.m16n8k32.row.col.f32.e4m3.e4m3.f32 "
                 "{%0,%1,%2,%3}, {%4,%5,%6,%7}, {%8,%9}, {%0,%1,%2,%3};\n"
                 : "+f"(c[0]), "+f"(c[1]), "+f"(c[2]), "+f"(c[3])
                 : "r"(a[0]), "r"(a[1]), "r"(a[2]), "r"(a[3]), "r"(b0), "r"(b1));
}
__device__ __forceinline__ void cpasync16(uint32_t dst, const void* src) {
    asm volatile("cp.async.cg.shared.global [%0], [%1], 16;\n" :: "r"(dst), "l"(src));
}
__device__ __forceinline__ uint16_t pack_e4m3(float hi, float lo) {
    uint16_t r;
    asm("cvt.rn.satfinite.e4m3x2.f32 %0, %1, %2;" : "=h"(r) : "f"(hi), "f"(lo));
    return r;
}

// ============================================================================
// P0: x fp32 -> bf16
// ============================================================================
__global__ __launch_bounds__(256) void k_prep(const float* __restrict__ x)
{
    size_t idx = ((size_t)blockIdx.x * 256 + threadIdx.x) * 8;
    float4 a = *(const float4*)(x + idx);
    float4 b = *(const float4*)(x + idx + 4);
    uint4 o;
    __nv_bfloat162* op = (__nv_bfloat162*)&o;
    op[0] = __floats2bfloat162_rn(a.x, a.y);
    op[1] = __floats2bfloat162_rn(a.z, a.w);
    op[2] = __floats2bfloat162_rn(b.x, b.y);
    op[3] = __floats2bfloat162_rn(b.z, b.w);
    *(uint4*)&g_X[idx] = o;
}

// ============================================================================
// P1: pack W into g_W [384 x 256] bf16 (+ bias)
// ============================================================================
__global__ __launch_bounds__(64) void k_prepw(
    const float* __restrict__ Wf, const float* __restrict__ bf,
    const float* __restrict__ Wg, const float* __restrict__ bg,
    const float* __restrict__ Wh, const float* __restrict__ bh)
{
    int row = blockIdx.x;
    const float* src = nullptr; float bias = 0.f;
    if (row < 32)       { src = Wf + (size_t)row * CC;        bias = bf[row]; }
    else if (row < 64)  { src = Wg + (size_t)(row - 32) * CC; bias = bg[row - 32]; }
    else if (row < 320) { src = Wh + (size_t)(row - 64) * CC; bias = bh[row - 64]; }
    for (int c = threadIdx.x * 4; c < CC; c += 64 * 4) {
#pragma unroll
        for (int k = 0; k < 4; k++)
            g_W[(size_t)row * CC + c + k] = src ? __float2bfloat16(src[c + k]) : __float2bfloat16(0.f);
    }
    if (threadIdx.x == 0) g_bias[row] = bias;
}

// ============================================================================
// K1: projections via bf16 mma (measured, unchanged)
// ============================================================================
#define AST 40
#define EST 136

__global__ __launch_bounds__(256, 2) void k_proj_mma()
{
    __shared__ __nv_bfloat16 As[2][128 * AST];
    __shared__ __nv_bfloat16 Bs[2][32 * EST];

    const int it = blockIdx.x, ct = blockIdx.y, b = blockIdx.z;
    const int tid = threadIdx.x;
    const int lane = tid & 31, warp = tid >> 5;
    const int wm = warp >> 2, wn = warp & 3;

    const __nv_bfloat16* Ag = g_W + (size_t)(ct * 128) * CC;
    const __nv_bfloat16* Bg = g_X + (size_t)b * CC * NN + it * 128;

    auto loadA = [&](int st, int kb) {
        int k0 = kb * 32;
        int row = tid >> 2, cid = (tid & 3) * 8;
#pragma unroll
        for (int r = 0; r < 2; r++) {
            int rr = row + r * 64;
            cpasync16(smem_u32(&As[st][rr * AST + cid]), Ag + (size_t)rr * CC + k0 + cid);
        }
    };
    auto loadB = [&](int st, int kb) {
        int k0 = kb * 32;
        int row = tid >> 4, cid = (tid & 15) * 8;
#pragma unroll
        for (int r = 0; r < 2; r++) {
            int rr = row + r * 16;
            cpasync16(smem_u32(&Bs[st][rr * EST + cid]), Bg + (size_t)(k0 + rr) * NN + cid);
        }
    };

    float acc[4][4][4];
#pragma unroll
    for (int m = 0; m < 4; m++)
#pragma unroll
        for (int n = 0; n < 4; n++)
#pragma unroll
            for (int e = 0; e < 4; e++) acc[m][n][e] = 0.f;

    loadA(0, 0); loadB(0, 0);
    asm volatile("cp.async.commit_group;\n");
    loadA(1, 1); loadB(1, 1);
    asm volatile("cp.async.commit_group;\n");

    const int grp = lane >> 3, lr = lane & 7;
    const int KB = CC / 32;

    for (int kb = 0; kb < KB; kb++) {
        asm volatile("cp.async.wait_group 1;\n");
        __syncthreads();
        const int st = kb & 1;
        const uint32_t smA = smem_u32(&As[st][0]);
        const uint32_t smB = smem_u32(&Bs[st][0]);
#pragma unroll
        for (int ks = 0; ks < 32; ks += 16) {
            uint32_t a[4][4];
#pragma unroll
            for (int mt = 0; mt < 4; mt++) {
                int row = wm * 64 + mt * 16 + (grp & 1) * 8 + lr;
                int col = ks + (grp >> 1) * 8;
                ldsm_x4(a[mt], smA + (row * AST + col) * 2);
            }
            uint32_t bfr[2][4];
#pragma unroll
            for (int nt = 0; nt < 2; nt++) {
                int krow = ks + (grp & 1) * 8 + lr;
                int ncol = wn * 32 + nt * 16 + (grp >> 1) * 8;
                ldsm_x4_t(bfr[nt], smB + (krow * EST + ncol) * 2);
            }
#pragma unroll
            for (int mt = 0; mt < 4; mt++)
#pragma unroll
                for (int nf = 0; nf < 4; nf++)
                    mma_bf16(acc[mt][nf], a[mt], bfr[nf >> 1][(nf & 1) * 2], bfr[nf >> 1][(nf & 1) * 2 + 1]);
        }
        __syncthreads();
        if (kb + 2 < KB) { loadA(st, kb + 2); loadB(st, kb + 2); }
        asm volatile("cp.async.commit_group;\n");
    }

#pragma unroll
    for (int mt = 0; mt < 4; mt++) {
#pragma unroll
        for (int nf = 0; nf < 4; nf++) {
            int col = it * 128 + wn * 32 + nf * 8 + (lane & 3) * 2;
#pragma unroll
            for (int h = 0; h < 2; h++) {
                int row = ct * 128 + wm * 64 + mt * 16 + (lane >> 2) + h * 8;
                if (row >= 320) continue;
                float bias = g_bias[row];
                __nv_bfloat16* dst;
                if (row < 32)      dst = g_F + ((size_t)(b * DKK + row)) * NN;
                else if (row < 64) dst = g_G + ((size_t)(b * DKK + row - 32)) * NN;
                else               dst = g_H + ((size_t)(b * CC + row - 64)) * NN;
                float v0 = acc[mt][nf][2 * h]     + bias;
                float v1 = acc[mt][nf][2 * h + 1] + bias;
                *(__nv_bfloat162*)(dst + col) = __floats2bfloat162_rn(v0, v1);
            }
        }
    }
}

// ============================================================================
// K2: S^T layout (m=i, n=j); E stored as e4m3 j-pairs; ex2.approx exp.
// (measured 49.4us, unchanged)
// ============================================================================
#define JST 72
#define FST 264

__global__ __launch_bounds__(256) void k_scores_mma()
{
    __shared__ __nv_bfloat16 gs[32 * JST];
    __shared__ __nv_bfloat16 fs[2][32 * FST];
    __shared__ float Zs[64];

    const int jt = blockIdx.x, b = blockIdx.y;
    const int tid = threadIdx.x;
    const int lane = tid & 31, warp = tid >> 5;
    const int wm = warp >> 1, wn = warp & 1;
    const int grp = lane >> 3, lr = lane & 7;
    const int j0 = jt * 64;

    {
        int row = tid >> 3, col = (tid & 7) * 8;
        uint4 v = *(const uint4*)(g_G + ((size_t)(b * DKK + row)) * NN + j0 + col);
        *(uint4*)&gs[row * JST + col] = v;
    }

    auto loadF = [&](int st, int ch) {
        const __nv_bfloat16* src = g_F + (size_t)b * DKK * NN + ch * 256;
#pragma unroll
        for (int r = 0; r < 4; r++) {
            int e = tid + r * 256;
            int row = e >> 5, col = (e & 31) * 8;
            cpasync16(smem_u32(&fs[st][row * FST + col]), src + (size_t)row * NN + col);
        }
    };

    loadF(0, 0);
    asm volatile("cp.async.commit_group;\n");
    loadF(1, 1);
    asm volatile("cp.async.commit_group;\n");
    __syncthreads();

    const uint32_t smG = smem_u32(gs);
    uint16_t* const E8b = g_E8 + (size_t)b * (NN / 2) * NN;

    float zacc[8];
#pragma unroll
    for (int r = 0; r < 8; r++) zacc[r] = 0.f;

    for (int ch = 0; ch < 16; ch++) {
        asm volatile("cp.async.wait_group 1;\n");
        __syncthreads();
        const int st = ch & 1;
        const uint32_t smF = smem_u32(&fs[st][0]);
        const int i0 = ch * 256;

        float acc[4][4][4];
#pragma unroll
        for (int m = 0; m < 4; m++)
#pragma unroll
            for (int n = 0; n < 4; n++)
#pragma unroll
                for (int e = 0; e < 4; e++) acc[m][n][e] = 0.f;

#pragma unroll
        for (int ks = 0; ks < 32; ks += 16) {
            uint32_t a[4][4];
#pragma unroll
            for (int mt = 0; mt < 4; mt++) {
                int row = ks + (grp >> 1) * 8 + lr;
                int col = wm * 64 + mt * 16 + (grp & 1) * 8;
                ldsm_x4_t(a[mt], smF + (row * FST + col) * 2);
            }
            uint32_t bfr[2][4];
#pragma unroll
            for (int nt = 0; nt < 2; nt++) {
                int krow = ks + (grp & 1) * 8 + lr;
                int ncol = wn * 32 + nt * 16 + (grp >> 1) * 8;
                ldsm_x4_t(bfr[nt], smG + (krow * JST + ncol) * 2);
            }
#pragma unroll
            for (int mt = 0; mt < 4; mt++)
#pragma unroll
                for (int nf = 0; nf < 4; nf++)
                    mma_bf16(acc[mt][nf], a[mt], bfr[nf >> 1][(nf & 1) * 2], bfr[nf >> 1][(nf & 1) * 2 + 1]);
        }

#pragma unroll
        for (int mt = 0; mt < 4; mt++) {
#pragma unroll
            for (int nf = 0; nf < 4; nf++) {
                int j = j0 + wn * 32 + nf * 8 + (lane & 3) * 2;
#pragma unroll
                for (int h = 0; h < 2; h++) {
                    int i = i0 + wm * 64 + mt * 16 + (lane >> 2) + h * 8;
                    float e0 = fexp(acc[mt][nf][2 * h]);
                    float e1 = fexp(acc[mt][nf][2 * h + 1]);
                    zacc[nf * 2 + 0] += e0;
                    zacc[nf * 2 + 1] += e1;
                    E8b[((size_t)(j >> 1) << 12) + i] = pack_e4m3(e1, e0);
                }
            }
        }
        __syncthreads();
        if (ch + 2 < 16) loadF(st, ch + 2);
        asm volatile("cp.async.commit_group;\n");
    }

    if (tid < 64) Zs[tid] = 0.f;
    __syncthreads();
#pragma unroll
    for (int r = 0; r < 8; r++) {
        zacc[r] += __shfl_xor_sync(0xffffffffu, zacc[r], 4);
        zacc[r] += __shfl_xor_sync(0xffffffffu, zacc[r], 8);
        zacc[r] += __shfl_xor_sync(0xffffffffu, zacc[r], 16);
    }
    if (lane < 4) {
#pragma unroll
        for (int nf = 0; nf < 4; nf++) {
#pragma unroll
            for (int p = 0; p < 2; p++)
                atomicAdd(&Zs[wn * 32 + nf * 8 + lane * 2 + p], zacc[nf * 2 + p]);
        }
    }
    __syncthreads();
    if (tid < 64) g_rZ[b * NN + j0 + tid] = 1.0f / Zs[tid];
}

// ============================================================================
// K2c: g_Hs[c][j] = e4m3( h[c][j] * 4096/Z[j] )
// ============================================================================
__global__ __launch_bounds__(256) void k_scaleh()
{
    size_t idx = ((size_t)blockIdx.x * 256 + threadIdx.x) * 8;
    int b = (int)(idx >> 20);
    int n = (int)(idx & (NN - 1));
    uint4 raw = *(uint4*)&g_H[idx];
    __nv_bfloat162* hp = (__nv_bfloat162*)&raw;
    const float* rz = g_rZ + b * NN + n;
    uint16_t h4[4];
#pragma unroll
    for (int p = 0; p < 4; p++) {
        float s0 = 4096.0f * rz[2 * p];
        float s1 = 4096.0f * rz[2 * p + 1];
        float v0 = __bfloat162float(__low2bfloat16(hp[p]))  * s0;
        float v1 = __bfloat162float(__high2bfloat16(hp[p])) * s1;
        h4[p] = pack_e4m3(v1, v0);
    }
    uint2 o;
    o.x = (uint32_t)h4[0] | ((uint32_t)h4[1] << 16);
    o.y = (uint32_t)h4[2] | ((uint32_t)h4[3] << 16);
    *(uint2*)&g_Hs[idx] = o;
}

// ============================================================================
// K3: out = (Hs @ E)/4096 + x via FP8 mma. CTA 128x128, k-chunk 32,
// 4-STAGE pipeline, prefetch distance 3 (wait_group 2), in-loop ldsm. occ 2.
// smem 41KB static.
// ============================================================================
#define K3A 24
#define K3E 136

__global__ __launch_bounds__(256, 2) void k_attn_out(
    const float* __restrict__ x, float* __restrict__ out)
{
    __shared__ uint16_t As[4][128 * K3A];   // 24.0 KB
    __shared__ uint16_t Es[4][16 * K3E];    // 17.0 KB

    const int it = blockIdx.x, ct = blockIdx.y, b = blockIdx.z;
    const int tid = threadIdx.x;
    const int lane = tid & 31, warp = tid >> 5;
    const int wm = warp >> 2, wn = warp & 3;

    const uint8_t*  Ag = g_Hs + (size_t)(b * CC + ct * 128) * NN;
    const uint16_t* Eg = g_E8 + (size_t)b * (NN / 2) * NN + it * 128;

    auto loadA = [&](int st, int kb) {
        int k0 = kb * 32;
        int row = tid >> 1, seg = (tid & 1) * 16;
        cpasync16(smem_u32(&As[st][row * K3A + (tid & 1) * 8]), Ag + (size_t)row * NN + k0 + seg);
    };
    auto loadE = [&](int st, int kb) {
        int kp0 = kb * 16;
        int row = tid >> 4, col = (tid & 15) * 8;
        cpasync16(smem_u32(&Es[st][row * K3E + col]), Eg + (size_t)(kp0 + row) * NN + col);
    };

    float acc[4][4][4];
#pragma unroll
    for (int m = 0; m < 4; m++)
#pragma unroll
        for (int n = 0; n < 4; n++)
#pragma unroll
            for (int e = 0; e < 4; e++) acc[m][n][e] = 0.f;

    loadA(0, 0); loadE(0, 0);
    asm volatile("cp.async.commit_group;\n");
    loadA(1, 1); loadE(1, 1);
    asm volatile("cp.async.commit_group;\n");
    loadA(2, 2); loadE(2, 2);
    asm volatile("cp.async.commit_group;\n");

    const int grp = lane >> 3, lr = lane & 7;
    const int KB = NN / 32;   // 128

    for (int kb = 0; kb < KB; kb++) {
        asm volatile("cp.async.wait_group 2;\n");   // chunk kb done; {kb+1,kb+2} pending
        __syncthreads();   // all warps finished reading stage (kb-1)%4 in iter kb-1

        if (kb + 3 < KB) {
            int st3 = (kb + 3) & 3;                 // == (kb-1)%4
            loadA(st3, kb + 3); loadE(st3, kb + 3);
        }
        asm volatile("cp.async.commit_group;\n");   // pending {kb+1,kb+2,kb+3}

        const int st = kb & 3;
        const uint32_t smA = smem_u32(&As[st][0]);
        const uint32_t smE = smem_u32(&Es[st][0]);

        uint32_t a[4][4];
#pragma unroll
        for (int mt = 0; mt < 4; mt++) {
            int row = wm * 64 + mt * 16 + (grp & 1) * 8 + lr;
            int col = (grp >> 1) * 8;
            ldsm_x4(a[mt], smA + (row * K3A + col) * 2);
        }
        uint32_t bfr[2][4];
#pragma unroll
        for (int nt = 0; nt < 2; nt++) {
            int krow = (grp & 1) * 8 + lr;
            int ncol = wn * 32 + nt * 16 + (grp >> 1) * 8;
            ldsm_x4_t(bfr[nt], smE + (krow * K3E + ncol) * 2);
        }
#pragma unroll
        for (int mt = 0; mt < 4; mt++)
#pragma unroll
            for (int nf = 0; nf < 4; nf++)
                mma_fp8(acc[mt][nf], a[mt], bfr[nf >> 1][(nf & 1) * 2], bfr[nf >> 1][(nf & 1) * 2 + 1]);
    }

    // epilogue: out = acc/4096 + x
    const float INVN = 1.0f / 4096.0f;
#pragma unroll
    for (int mt = 0; mt < 4; mt++) {
#pragma unroll
        for (int nf = 0; nf < 4; nf++) {
            int row = ct * 128 + wm * 64 + mt * 16 + (lane >> 2);
            int col = it * 128 + wn * 32 + nf * 8 + (lane & 3) * 2;
            size_t base = ((size_t)(b * CC + row)) * NN + col;
            float2 xv = *(const float2*)(x + base);
            float2 o0;
            o0.x = fmaf(acc[mt][nf][0], INVN, xv.x);
            o0.y = fmaf(acc[mt][nf][1], INVN, xv.y);
            *(float2*)(out + base) = o0;
            size_t base2 = base + (size_t)8 * NN;
            float2 xv2 = *(const float2*)(x + base2);
            float2 o1;
            o1.x = fmaf(acc[mt][nf][2], INVN, xv2.x);
            o1.y = fmaf(acc[mt][nf][3], INVN, xv2.y);
            *(float2*)(out + base2) = o1;
        }
    }
}

// ============================================================================
extern "C" void kernel_launch(void* const* d_in, const int* in_sizes, int n_in,
                              void* d_out, int out_size)
{
    const float* x  = (const float*)d_in[0];
    const float* Wf = (const float*)d_in[1];
    const float* bf = (const float*)d_in[2];
    const float* Wg = (const float*)d_in[3];
    const float* bg = (const float*)d_in[4];
    const float* Wh = (const float*)d_in[5];
    const float* bh = (const float*)d_in[6];
    float* out = (float*)d_out;

    k_prep      <<<2048, 256>>>(x);
    k_prepw     <<<384, 64>>>(Wf, bf, Wg, bg, Wh, bh);
    k_proj_mma  <<<dim3(32, 3, 4), 256>>>();
    k_scores_mma<<<dim3(64, 4),    256>>>();
    k_scaleh    <<<2048,           256>>>();
    k_attn_out  <<<dim3(32, 2, 4), 256>>>(x, out);
}